// round 3
// baseline (speedup 1.0000x reference)
#include <cuda_runtime.h>
#include <math.h>

#define N_NODES 50000
#define N_EDGES 1600000
#define HID 32
#define HOR 12

// ---------------- scratch (static device allocation, no cudaMalloc) ----------------
__device__ float g_deg[N_NODES];
__device__ float g_dinv[N_NODES];
__device__ float g_LX[N_NODES * HID];   // L @ X
__device__ float g_Lh[N_NODES * HID];   // L @ h0
__device__ int   g_hflag;               // any(h0 != 0)

// ---------------- init: zero scratch ----------------
__global__ void k_init() {
    int i = blockIdx.x * blockDim.x + threadIdx.x;
    if (i < N_NODES * HID) { g_LX[i] = 0.f; g_Lh[i] = 0.f; }
    if (i < N_NODES) g_deg[i] = 0.f;
    if (i == 0) g_hflag = 0;
}

// ---------------- deg = segment_sum(w, src); also probe h0 for nonzeros ----------------
__global__ void k_deg(const int* __restrict__ src,
                      const float* __restrict__ w,
                      const float* __restrict__ h0) {
    int i = blockIdx.x * blockDim.x + threadIdx.x;
    if (i < N_EDGES) {
        int s = src[i];
        if (s >= 0 && s < N_NODES) atomicAdd(&g_deg[s], w[i]);
    }
    if (i < N_NODES * HID) {
        if (h0[i] != 0.f) g_hflag = 1;   // benign race, deterministic outcome
    }
}

__global__ void k_dinv() {
    int i = blockIdx.x * blockDim.x + threadIdx.x;
    if (i < N_NODES) {
        float d = g_deg[i];
        g_dinv[i] = d > 0.f ? rsqrtf(d) : 0.f;
    }
}

// ---------------- edge aggregation: LX[dst] += nw * X[src]  (and Lh if h0 != 0) ----------------
// one warp handles 8 consecutive edges; lane = feature index (coalesced 128B gathers/atomics)
__global__ void k_edge(const int* __restrict__ src,
                       const int* __restrict__ dst,
                       const float* __restrict__ w,
                       const float* __restrict__ x,
                       const float* __restrict__ h0) {
    int lane = threadIdx.x & 31;
    long long wid = (long long)(blockIdx.x * blockDim.x + threadIdx.x) >> 5;
    long long base = wid * 8;
    if (base >= N_EDGES) return;

    int sl = 0, dl = 0;
    float nvl = 0.f;
    if (lane < 8) {
        long long e = base + lane;
        if (e < N_EDGES) {
            int s = src[e];
            int d = dst[e];
            if (s >= 0 && s < N_NODES && d >= 0 && d < N_NODES) {
                sl = s;
                dl = d;
                nvl = -g_dinv[s] * w[e] * g_dinv[d];
            }
        }
    }
    int hf = g_hflag;
    int cnt = (int)min((long long)8, (long long)N_EDGES - base);

    #pragma unroll
    for (int i = 0; i < 8; i++) {
        if (i >= cnt) break;
        int   s  = __shfl_sync(0xffffffffu, sl, i);
        int   d  = __shfl_sync(0xffffffffu, dl, i);
        float nv = __shfl_sync(0xffffffffu, nvl, i);
        if (nv != 0.f) {
            float xv = __ldg(&x[(size_t)s * HID + lane]);
            atomicAdd(&g_LX[d * HID + lane], nv * xv);
            if (hf) {
                float hv = __ldg(&h0[(size_t)s * HID + lane]);
                atomicAdd(&g_Lh[d * HID + lane], nv * hv);
            }
        }
    }
}

// ---------------- gates + LSTM cell + linear head, fused ----------------
// block = 128 threads (4 warps); each warp owns 4 nodes; lane = hidden index j.
// 16 nodes per block. Wx cached in smem; Wh (only needed if h0 != 0) read via L1.
__global__ void __launch_bounds__(128) k_gates(
        const float* __restrict__ x,
        const float* __restrict__ h0,
        const float* __restrict__ c0,
        const float* __restrict__ Wx,   // [4][2][32][32]
        const float* __restrict__ bx,   // [4][32]
        const float* __restrict__ Wh,   // [4][2][32][32]
        const float* __restrict__ bh,   // [4][32]
        const float* __restrict__ wc,   // [3][32]
        const float* __restrict__ b,    // [4][32]
        const float* __restrict__ Wl,   // [32][12]
        const float* __restrict__ bl,   // [12]
        float* __restrict__ out) {
    __shared__ float sWx[4 * 2 * 32 * 32];   // 8192 floats
    __shared__ float sU[16 * 4 * 32];        // [node][mat: X,LX,h0,Lh][k]
    __shared__ float sWl[HID * HOR];
    __shared__ float sbsum[4 * HID];
    __shared__ float swc[3 * HID];
    __shared__ float sbl[HOR];

    int tid = threadIdx.x;
    int nodeBase = blockIdx.x * 16;
    int hf = g_hflag;

    for (int i = tid; i < 8192; i += 128) sWx[i] = Wx[i];
    for (int i = tid; i < HID * HOR; i += 128) sWl[i] = Wl[i];
    if (tid < 4 * HID) sbsum[tid] = bx[tid] + bh[tid] + b[tid];
    if (tid < 3 * HID) swc[tid] = wc[tid];
    if (tid < HOR)     sbl[tid] = bl[tid];

    // stage U tile: X and LX always; h0/Lh only if flag
    for (int i = tid; i < 16 * 2 * 32; i += 128) {
        int n = i >> 6, m = (i >> 5) & 1, k = i & 31;
        int node = nodeBase + n;
        float v = 0.f;
        if (node < N_NODES) v = m ? g_LX[node * HID + k] : x[node * HID + k];
        sU[(n * 4 + m) * 32 + k] = v;
    }
    if (hf) {
        for (int i = tid; i < 16 * 2 * 32; i += 128) {
            int n = i >> 6, m = (i >> 5) & 1, k = i & 31;
            int node = nodeBase + n;
            float v = 0.f;
            if (node < N_NODES) v = m ? g_Lh[node * HID + k] : h0[node * HID + k];
            sU[(n * 4 + 2 + m) * 32 + k] = v;
        }
    }
    __syncthreads();

    int warp = tid >> 5;
    int j = tid & 31;
    int nb = warp * 4;   // local node base

    float acc[4][4];     // [node][gate]
    #pragma unroll
    for (int n = 0; n < 4; n++)
        #pragma unroll
        for (int g = 0; g < 4; g++) acc[n][g] = 0.f;

    if (!hf) {
        #pragma unroll
        for (int k = 0; k < 32; k++) {
            float wa[4], wb[4];
            #pragma unroll
            for (int g = 0; g < 4; g++) {
                wa[g] = sWx[g * 2048 +        k * 32 + j];
                wb[g] = sWx[g * 2048 + 1024 + k * 32 + j];
            }
            #pragma unroll
            for (int n = 0; n < 4; n++) {
                float xv  = sU[((nb + n) * 4 + 0) * 32 + k];
                float lxv = sU[((nb + n) * 4 + 1) * 32 + k];
                #pragma unroll
                for (int g = 0; g < 4; g++)
                    acc[n][g] += xv * wa[g] + lxv * wb[g];
            }
        }
    } else {
        #pragma unroll
        for (int k = 0; k < 32; k++) {
            float wa[4], wb[4], wha[4], whb[4];
            #pragma unroll
            for (int g = 0; g < 4; g++) {
                wa[g]  = sWx[g * 2048 +        k * 32 + j];
                wb[g]  = sWx[g * 2048 + 1024 + k * 32 + j];
                wha[g] = __ldg(&Wh[g * 2048 +        k * 32 + j]);
                whb[g] = __ldg(&Wh[g * 2048 + 1024 + k * 32 + j]);
            }
            #pragma unroll
            for (int n = 0; n < 4; n++) {
                float xv  = sU[((nb + n) * 4 + 0) * 32 + k];
                float lxv = sU[((nb + n) * 4 + 1) * 32 + k];
                float hv  = sU[((nb + n) * 4 + 2) * 32 + k];
                float lhv = sU[((nb + n) * 4 + 3) * 32 + k];
                #pragma unroll
                for (int g = 0; g < 4; g++)
                    acc[n][g] += xv * wa[g] + lxv * wb[g] + hv * wha[g] + lhv * whb[g];
            }
        }
    }

    float* oh = out;                               // h: [N][12]
    float* oH = out + (size_t)N_NODES * HOR;       // H: [N][32]
    float* oC = oH + (size_t)N_NODES * HID;        // C: [N][32]

    #pragma unroll
    for (int n = 0; n < 4; n++) {
        int node = nodeBase + nb + n;
        if (node < N_NODES) {                       // warp-uniform
            float c0v = c0[node * HID + j];
            float preI = acc[n][0] + sbsum[0 * 32 + j] + swc[0 * 32 + j] * c0v;
            float preF = acc[n][1] + sbsum[1 * 32 + j] + swc[1 * 32 + j] * c0v;
            float preT = acc[n][2] + sbsum[2 * 32 + j];
            float I  = 1.f / (1.f + __expf(-preI));
            float Fg = 1.f / (1.f + __expf(-preF));
            float T  = tanhf(preT);
            float C  = Fg * c0v + I * T;
            float preO = acc[n][3] + sbsum[3 * 32 + j] + swc[2 * 32 + j] * C;
            float O  = 1.f / (1.f + __expf(-preO));
            float H  = O * tanhf(C);

            oH[node * HID + j] = H;
            oC[node * HID + j] = C;

            // head: h[t] = sum_j relu(H_j) * Wl[j][t] + bl[t]
            float rH = fmaxf(H, 0.f);
            float keep = 0.f;
            #pragma unroll
            for (int t = 0; t < HOR; t++) {
                float s = rH * sWl[j * HOR + t];
                s += __shfl_xor_sync(0xffffffffu, s, 16);
                s += __shfl_xor_sync(0xffffffffu, s, 8);
                s += __shfl_xor_sync(0xffffffffu, s, 4);
                s += __shfl_xor_sync(0xffffffffu, s, 2);
                s += __shfl_xor_sync(0xffffffffu, s, 1);
                if (j == t) keep = s + sbl[t];
            }
            if (j < HOR) oh[node * HOR + j] = keep;
        }
    }
}

// ---------------- launch ----------------
extern "C" void kernel_launch(void* const* d_in, const int* in_sizes, int n_in,
                              void* d_out, int out_size) {
    // Resolve input ordering robustly. edge_index is the unique input with
    // 2*N_EDGES (= 3,200,000) elements.
    //   insertion order:    x, edge_index, edge_weight, Wx, bx, Wh, bh, wc, b, W_lin, b_lin, h0, c0
    //   alphabetical order: W_lin, Wh, Wx, b, b_lin, bh, bx, c0, edge_index, edge_weight, h0, wc, x
    int iX, iEI, iEW, iWx, iBx, iWh, iBh, iWc, iB, iWl, iBl, iH0, iC0;
    if (n_in > 8 && in_sizes[8] == 2 * N_EDGES) {
        // alphabetical
        iWl = 0; iWh = 1; iWx = 2; iB = 3; iBl = 4; iBh = 5; iBx = 6;
        iC0 = 7; iEI = 8; iEW = 9; iH0 = 10; iWc = 11; iX = 12;
    } else {
        // insertion (reference signature) order
        iX = 0; iEI = 1; iEW = 2; iWx = 3; iBx = 4; iWh = 5; iBh = 6;
        iWc = 7; iB = 8; iWl = 9; iBl = 10; iH0 = 11; iC0 = 12;
    }

    const float* x    = (const float*)d_in[iX];
    const int*   ei   = (const int*)d_in[iEI];     // JAX x64 disabled: int32!
    const float* ew   = (const float*)d_in[iEW];
    const float* Wx   = (const float*)d_in[iWx];
    const float* bx   = (const float*)d_in[iBx];
    const float* Wh   = (const float*)d_in[iWh];
    const float* bh   = (const float*)d_in[iBh];
    const float* wc   = (const float*)d_in[iWc];
    const float* b    = (const float*)d_in[iB];
    const float* Wl   = (const float*)d_in[iWl];
    const float* bl   = (const float*)d_in[iBl];
    const float* h0   = (const float*)d_in[iH0];
    const float* c0   = (const float*)d_in[iC0];
    float*       out  = (float*)d_out;

    const int* src = ei;
    const int* dst = ei + N_EDGES;

    k_init<<<(N_NODES * HID + 255) / 256, 256>>>();
    k_deg<<<(N_EDGES + 255) / 256, 256>>>(src, ew, h0);
    k_dinv<<<(N_NODES + 255) / 256, 256>>>();

    // one warp per 8 edges
    long long warps = (N_EDGES + 7) / 8;
    long long threads = warps * 32;
    k_edge<<<(int)((threads + 255) / 256), 256>>>(src, dst, ew, x, h0);

    k_gates<<<(N_NODES + 15) / 16, 128>>>(x, h0, c0, Wx, bx, Wh, bh, wc, b, Wl, bl, out);
}